// round 3
// baseline (speedup 1.0000x reference)
#include <cuda_runtime.h>
#include <math.h>

#define BB 4
#define NQ 64
#define NN 1024
#define DD 768
#define HH 8
#define DH 96
#define RANK 64
#define QR 4096
#define LN_EPS 1e-5f

// ---------------- scratch (static device allocations; no cudaMalloc) ----------------
__device__ float g_q [BB*NQ*DD];        // 0.75 MB
__device__ float g_k [BB*NN*DD];        // 12.6 MB
__device__ float g_h1[(size_t)BB*NN*QR]; // 67 MB  (post-LN this is vmid[b,n,q,r])
__device__ float g_sim[(size_t)BB*HH*NQ*NN]; // 8.4 MB
__device__ float g_t [BB*NQ*HH*RANK];   // 0.5 MB
__device__ float g_op[BB*NQ*DD];        // 0.75 MB

// ---------------- generic 128x128x8 fp32 SGEMM (row-major, dims % 128/8 == 0) ------
__global__ __launch_bounds__(256) void sgemm128(const float* __restrict__ A,
                                                const float* __restrict__ Bm,
                                                float* __restrict__ C,
                                                int M, int Nn, int K)
{
    __shared__ __align__(16) float As[8][128];
    __shared__ __align__(16) float Bs[8][128];
    int tid = threadIdx.x;
    int tx = tid & 15, ty = tid >> 4;
    int m0 = blockIdx.y * 128, n0 = blockIdx.x * 128;

    float acc[8][8];
    #pragma unroll
    for (int i = 0; i < 8; i++)
        #pragma unroll
        for (int j = 0; j < 8; j++) acc[i][j] = 0.f;

    int arow = tid >> 1, akk = (tid & 1) * 4;
    int brow = tid >> 5, bcol = (tid & 31) * 4;
    const float* Aptr = A + (size_t)(m0 + arow) * K + akk;
    const float* Bptr = Bm + (size_t)brow * Nn + n0 + bcol;

    for (int kt = 0; kt < K; kt += 8) {
        float4 av = *(const float4*)(Aptr + kt);
        float4 bv = *(const float4*)(Bptr + (size_t)kt * Nn);
        As[akk + 0][arow] = av.x;
        As[akk + 1][arow] = av.y;
        As[akk + 2][arow] = av.z;
        As[akk + 3][arow] = av.w;
        *(float4*)&Bs[brow][bcol] = bv;
        __syncthreads();
        #pragma unroll
        for (int k = 0; k < 8; k++) {
            float a[8], b[8];
            *(float4*)&a[0] = *(const float4*)&As[k][ty * 8];
            *(float4*)&a[4] = *(const float4*)&As[k][ty * 8 + 4];
            *(float4*)&b[0] = *(const float4*)&Bs[k][tx * 8];
            *(float4*)&b[4] = *(const float4*)&Bs[k][tx * 8 + 4];
            #pragma unroll
            for (int i = 0; i < 8; i++)
                #pragma unroll
                for (int j = 0; j < 8; j++)
                    acc[i][j] = fmaf(a[i], b[j], acc[i][j]);
        }
        __syncthreads();
    }

    float* Cp = C + (size_t)(m0 + ty * 8) * Nn + n0 + tx * 8;
    #pragma unroll
    for (int i = 0; i < 8; i++) {
        *(float4*)(Cp + (size_t)i * Nn)     = *(float4*)&acc[i][0];
        *(float4*)(Cp + (size_t)i * Nn + 4) = *(float4*)&acc[i][4];
    }
}

// ---------------- LayerNorm over QR=4096 per (b,n) row, in place on g_h1 ----------
__global__ __launch_bounds__(256) void ln_kernel(const float* __restrict__ gam,
                                                 const float* __restrict__ bet)
{
    int row = blockIdx.x;
    float* p = g_h1 + (size_t)row * QR;
    __shared__ float red[256];
    int tid = threadIdx.x;

    float s = 0.f;
    for (int c = tid; c < QR; c += 256) s += p[c];
    red[tid] = s; __syncthreads();
    for (int o = 128; o > 0; o >>= 1) {
        if (tid < o) red[tid] += red[tid + o];
        __syncthreads();
    }
    float mean = red[0] * (1.0f / QR);
    __syncthreads();

    float vs = 0.f;
    for (int c = tid; c < QR; c += 256) { float d = p[c] - mean; vs += d * d; }
    red[tid] = vs; __syncthreads();
    for (int o = 128; o > 0; o >>= 1) {
        if (tid < o) red[tid] += red[tid + o];
        __syncthreads();
    }
    float inv = rsqrtf(red[0] * (1.0f / QR) + LN_EPS);

    for (int c = tid; c < QR; c += 256)
        p[c] = (p[c] - mean) * inv * gam[c] + bet[c];
}

// ---------------- sim[b,h,i,j] = (1/sqrt(dh)) * q_h[i,:]·k_h[j,:] -----------------
__global__ __launch_bounds__(256) void sim_kernel()
{
    __shared__ float qs[64][97];
    __shared__ float ks[32][97];
    int jt = blockIdx.x, h = blockIdx.y, b = blockIdx.z;
    int tid = threadIdx.x;

    for (int idx = tid; idx < 64 * 96; idx += 256) {
        int i = idx / 96, c = idx % 96;
        qs[i][c] = g_q[(size_t)(b * NQ + i) * DD + h * DH + c];
    }
    for (int idx = tid; idx < 32 * 96; idx += 256) {
        int j = idx / 96, c = idx % 96;
        ks[j][c] = g_k[(size_t)(b * NN + jt * 32 + j) * DD + h * DH + c];
    }
    __syncthreads();

    int tx = tid & 15, ty = tid >> 4;
    float acc[4][2];
    #pragma unroll
    for (int ii = 0; ii < 4; ii++) { acc[ii][0] = 0.f; acc[ii][1] = 0.f; }

    #pragma unroll 4
    for (int c = 0; c < 96; c++) {
        float qv[4], kv[2];
        #pragma unroll
        for (int ii = 0; ii < 4; ii++) qv[ii] = qs[ty * 4 + ii][c];
        kv[0] = ks[tx * 2][c];
        kv[1] = ks[tx * 2 + 1][c];
        #pragma unroll
        for (int ii = 0; ii < 4; ii++) {
            acc[ii][0] = fmaf(qv[ii], kv[0], acc[ii][0]);
            acc[ii][1] = fmaf(qv[ii], kv[1], acc[ii][1]);
        }
    }

    const float sc = 0.10206207261596577f; // 96^-0.5
    #pragma unroll
    for (int ii = 0; ii < 4; ii++) {
        #pragma unroll
        for (int jj = 0; jj < 2; jj++) {
            int i = ty * 4 + ii, j = jt * 32 + tx * 2 + jj;
            g_sim[((size_t)(b * HH + h) * NQ + i) * NN + j] = acc[ii][jj] * sc;
        }
    }
}

// ---------------- softmax over j (row length 1024), in place on g_sim -------------
__global__ __launch_bounds__(256) void softmax_kernel()
{
    int row = blockIdx.x;
    float* p = g_sim + (size_t)row * NN;
    __shared__ float red[256];
    int tid = threadIdx.x;

    float m = -1e30f;
    for (int j = tid; j < NN; j += 256) m = fmaxf(m, p[j]);
    red[tid] = m; __syncthreads();
    for (int o = 128; o > 0; o >>= 1) {
        if (tid < o) red[tid] = fmaxf(red[tid], red[tid + o]);
        __syncthreads();
    }
    m = red[0]; __syncthreads();

    float s = 0.f;
    for (int j = tid; j < NN; j += 256) {
        float e = __expf(p[j] - m);
        p[j] = e;
        s += e;
    }
    red[tid] = s; __syncthreads();
    for (int o = 128; o > 0; o >>= 1) {
        if (tid < o) red[tid] += red[tid + o];
        __syncthreads();
    }
    float inv = 1.0f / red[0];
    for (int j = tid; j < NN; j += 256) p[j] *= inv;
}

// ---------------- t[b,i,h,r] = sum_j attn[b,h,i,j] * vmid[b,j,i,r] ----------------
__global__ __launch_bounds__(256) void t_kernel()
{
    int b = blockIdx.x >> 6, i = blockIdx.x & 63;
    __shared__ float attn_s[HH * NN];   // 32 KB
    __shared__ float red[4 * HH * 64]; // 8 KB
    int tid = threadIdx.x;

    for (int idx = tid; idx < HH * NN; idx += 256) {
        int h = idx >> 10, j = idx & 1023;
        attn_s[idx] = g_sim[((size_t)(b * HH + h) * NQ + i) * NN + j];
    }
    __syncthreads();

    int r = tid & 63, c4 = tid >> 6;
    float acc[8];
    #pragma unroll
    for (int h = 0; h < 8; h++) acc[h] = 0.f;

    const float* vp = g_h1 + (size_t)b * NN * QR + i * RANK + r;
    int j0 = c4 * 256;
    #pragma unroll 4
    for (int j = j0; j < j0 + 256; j++) {
        float vm = vp[(size_t)j * QR];
        #pragma unroll
        for (int h = 0; h < 8; h++)
            acc[h] = fmaf(attn_s[h * NN + j], vm, acc[h]);
    }
    #pragma unroll
    for (int h = 0; h < 8; h++) red[(c4 * 8 + h) * 64 + r] = acc[h];
    __syncthreads();

    for (int idx = tid; idx < 8 * 64; idx += 256) {
        int h = idx >> 6, r2 = idx & 63;
        float s = red[(0 * 8 + h) * 64 + r2] + red[(1 * 8 + h) * 64 + r2]
                + red[(2 * 8 + h) * 64 + r2] + red[(3 * 8 + h) * 64 + r2];
        g_t[((size_t)(b * NQ + i) * HH + h) * 64 + r2] = s;
    }
}

// ---------------- out_pre[b,i,d] = sum_r t[b,i,head(d),r] * Wc[i,r,d] -------------
__global__ __launch_bounds__(256) void conv_kernel(const float* __restrict__ Wc)
{
    int b = blockIdx.x >> 6, i = blockIdx.x & 63;
    __shared__ float ts[HH * RANK];
    int tid = threadIdx.x;
    for (int idx = tid; idx < HH * RANK; idx += 256)
        ts[idx] = g_t[(size_t)(b * NQ + i) * (HH * RANK) + idx];
    __syncthreads();

    for (int dd = tid; dd < DD; dd += 256) {
        int h = dd / DH;
        float acc = 0.f;
        const float* wp = Wc + (size_t)i * RANK * DD + dd;
        #pragma unroll 8
        for (int rr = 0; rr < RANK; rr++)
            acc = fmaf(ts[h * RANK + rr], wp[(size_t)rr * DD], acc);
        g_op[(size_t)(b * NQ + i) * DD + dd] = acc;
    }
}

// ---------------- launch ----------------
extern "C" void kernel_launch(void* const* d_in, const int* in_sizes, int n_in,
                              void* d_out, int out_size)
{
    const float* x       = (const float*)d_in[0];
    const float* context = (const float*)d_in[1];
    const float* Wq      = (const float*)d_in[2];
    const float* Wk      = (const float*)d_in[3];
    const float* Wv1     = (const float*)d_in[4];
    const float* ln_g    = (const float*)d_in[5];
    const float* ln_b    = (const float*)d_in[6];
    const float* Wc      = (const float*)d_in[7];
    const float* Wout    = (const float*)d_in[8];
    float* out = (float*)d_out;

    float *pq, *pk, *ph1, *pop;
    cudaGetSymbolAddress((void**)&pq,  g_q);
    cudaGetSymbolAddress((void**)&pk,  g_k);
    cudaGetSymbolAddress((void**)&ph1, g_h1);
    cudaGetSymbolAddress((void**)&pop, g_op);

    // q = x @ Wq                 [256,768] @ [768,768]
    sgemm128<<<dim3(DD / 128, (BB * NQ) / 128), 256>>>(x, Wq, pq, BB * NQ, DD, DD);
    // k = context @ Wk           [4096,768] @ [768,768]
    sgemm128<<<dim3(DD / 128, (BB * NN) / 128), 256>>>(context, Wk, pk, BB * NN, DD, DD);
    // h1 = context @ Wv1         [4096,768] @ [768,4096]   (dominant)
    sgemm128<<<dim3(QR / 128, (BB * NN) / 128), 256>>>(context, Wv1, ph1, BB * NN, QR, DD);
    // LayerNorm rows of h1 (-> vmid)
    ln_kernel<<<BB * NN, 256>>>(ln_g, ln_b);
    // sim = scaled q·k per head
    sim_kernel<<<dim3(NN / 32, HH, BB), 256>>>();
    // softmax over keys
    softmax_kernel<<<BB * HH * NQ, 256>>>();
    // t = attn @ vmid (rank space, per query)
    t_kernel<<<BB * NQ, 256>>>();
    // out_pre = t contracted with Wc (rank -> d)
    conv_kernel<<<BB * NQ, 256>>>(Wc);
    // out = out_pre @ Wout
    sgemm128<<<dim3(DD / 128, (BB * NQ) / 128), 256>>>(pop, Wout, out, BB * NQ, DD, DD);
}

// round 4
// speedup vs baseline: 2.6839x; 2.6839x over previous
#include <cuda_runtime.h>
#include <math.h>
#include <stdint.h>

#define BB 4
#define NQ 64
#define NN 1024
#define DD 768
#define HH 8
#define DH 96
#define RANK 64
#define QR 4096
#define LN_EPS 1e-5f

// ---------------- scratch (static device allocations; no cudaMalloc) ----------------
__device__ float g_q [BB*NQ*DD];             // 0.75 MB
__device__ float g_k [BB*NN*DD];             // 12.6 MB
__device__ float g_h1[(size_t)BB*NN*QR];     // 67 MB  (post-LN this is vmid[b,n,q,r])
__device__ float g_sim[(size_t)BB*HH*NQ*NN]; // 8.4 MB
__device__ float g_t [BB*NQ*HH*RANK];        // 0.5 MB
__device__ float g_op[BB*NQ*DD];             // 0.75 MB

// ---------------- tf32 helpers ----------------
__device__ __forceinline__ float to_tf32(float x) {
    uint32_t u;
    asm("cvt.rna.tf32.f32 %0, %1;" : "=r"(u) : "f"(x));
    return __uint_as_float(u);
}

__device__ __forceinline__ void mma_tf32(float* d, const uint32_t* a, const uint32_t* b) {
    asm volatile("mma.sync.aligned.m16n8k8.row.col.f32.tf32.tf32.f32 "
                 "{%0,%1,%2,%3}, {%4,%5,%6,%7}, {%8,%9}, {%0,%1,%2,%3};"
                 : "+f"(d[0]), "+f"(d[1]), "+f"(d[2]), "+f"(d[3])
                 : "r"(a[0]), "r"(a[1]), "r"(a[2]), "r"(a[3]),
                   "r"(b[0]), "r"(b[1]));
}

// ---------------- 128x128 tf32 tensor-core GEMM (row-major; M%128==0 ok for M=256,
//                  N%128==0, K%32==0) ----------------
// Block: 256 threads = 8 warps (4 warp-rows x 2 warp-cols), warp tile 32x64.
// Per k8 step: 2 A-frags (m16) x 8 B-frags (n8) -> 16 mma.m16n8k8.
// As[m][36]: fragment LDS bank = (4g+tg)%32  -> bijective, conflict-free.
// Bs[k][136]: fragment LDS bank = (8tg+g)%32 -> bijective, conflict-free.
__global__ __launch_bounds__(256) void tgemm128(const float* __restrict__ A,
                                                const float* __restrict__ Bm,
                                                float* __restrict__ C,
                                                int M, int Nn, int K)
{
    __shared__ __align__(16) float As[128][36];
    __shared__ __align__(16) float Bs[32][136];

    int tid  = threadIdx.x;
    int warp = tid >> 5, lane = tid & 31;
    int g = lane >> 2, tg = lane & 3;
    int wm = (warp >> 1) * 32;      // warp row offset (0,32,64,96)
    int wn = (warp & 1) * 64;       // warp col offset (0,64)
    int m0 = blockIdx.y * 128, n0 = blockIdx.x * 128;

    float acc[2][8][4];
    #pragma unroll
    for (int mi = 0; mi < 2; mi++)
        #pragma unroll
        for (int ni = 0; ni < 8; ni++)
            #pragma unroll
            for (int c = 0; c < 4; c++) acc[mi][ni][c] = 0.f;

    for (int kt = 0; kt < K; kt += 32) {
        // gmem loads into registers (overlap with previous chunk's compute tail)
        float4 av[4], bv[4];
        #pragma unroll
        for (int l = 0; l < 4; l++) {
            int fl = tid + l * 256;
            int ar = fl >> 3, ac = (fl & 7) * 4;         // A: 128 rows x 8 float4
            av[l] = *(const float4*)(A + (size_t)(m0 + ar) * K + kt + ac);
            int br = fl >> 5, bc = (fl & 31) * 4;        // B: 32 rows x 32 float4
            bv[l] = *(const float4*)(Bm + (size_t)(kt + br) * Nn + n0 + bc);
        }
        __syncthreads();
        #pragma unroll
        for (int l = 0; l < 4; l++) {
            int fl = tid + l * 256;
            int ar = fl >> 3, ac = (fl & 7) * 4;
            av[l].x = to_tf32(av[l].x); av[l].y = to_tf32(av[l].y);
            av[l].z = to_tf32(av[l].z); av[l].w = to_tf32(av[l].w);
            *(float4*)&As[ar][ac] = av[l];
            int br = fl >> 5, bc = (fl & 31) * 4;
            bv[l].x = to_tf32(bv[l].x); bv[l].y = to_tf32(bv[l].y);
            bv[l].z = to_tf32(bv[l].z); bv[l].w = to_tf32(bv[l].w);
            *(float4*)&Bs[br][bc] = bv[l];
        }
        __syncthreads();

        #pragma unroll
        for (int ks = 0; ks < 4; ks++) {
            int kk = ks * 8;
            uint32_t af[2][4], bf[8][2];
            #pragma unroll
            for (int mi = 0; mi < 2; mi++) {
                int mr = wm + mi * 16 + g;
                af[mi][0] = __float_as_uint(As[mr    ][kk + tg    ]);
                af[mi][1] = __float_as_uint(As[mr + 8][kk + tg    ]);
                af[mi][2] = __float_as_uint(As[mr    ][kk + tg + 4]);
                af[mi][3] = __float_as_uint(As[mr + 8][kk + tg + 4]);
            }
            #pragma unroll
            for (int ni = 0; ni < 8; ni++) {
                int nc = wn + ni * 8 + g;
                bf[ni][0] = __float_as_uint(Bs[kk + tg    ][nc]);
                bf[ni][1] = __float_as_uint(Bs[kk + tg + 4][nc]);
            }
            #pragma unroll
            for (int mi = 0; mi < 2; mi++)
                #pragma unroll
                for (int ni = 0; ni < 8; ni++)
                    mma_tf32(acc[mi][ni], af[mi], bf[ni]);
        }
    }

    // epilogue: c0:(g,2tg) c1:(g,2tg+1) c2:(g+8,2tg) c3:(g+8,2tg+1)
    #pragma unroll
    for (int mi = 0; mi < 2; mi++) {
        int r0 = m0 + wm + mi * 16 + g;
        #pragma unroll
        for (int ni = 0; ni < 8; ni++) {
            int c = n0 + wn + ni * 8 + 2 * tg;
            *(float2*)(C + (size_t)r0 * Nn + c)       = make_float2(acc[mi][ni][0], acc[mi][ni][1]);
            *(float2*)(C + (size_t)(r0 + 8) * Nn + c) = make_float2(acc[mi][ni][2], acc[mi][ni][3]);
        }
    }
}

// ---------------- LayerNorm over QR=4096 per (b,n) row, in place on g_h1 ----------
__global__ __launch_bounds__(256) void ln_kernel(const float* __restrict__ gam,
                                                 const float* __restrict__ bet)
{
    int row = blockIdx.x;
    float4* p = (float4*)(g_h1 + (size_t)row * QR);   // 1024 float4
    const float4* g4 = (const float4*)gam;
    const float4* b4 = (const float4*)bet;
    __shared__ float red[256];
    int tid = threadIdx.x;

    float s = 0.f;
    for (int c = tid; c < QR / 4; c += 256) {
        float4 v = p[c];
        s += v.x + v.y + v.z + v.w;
    }
    red[tid] = s; __syncthreads();
    for (int o = 128; o > 0; o >>= 1) {
        if (tid < o) red[tid] += red[tid + o];
        __syncthreads();
    }
    float mean = red[0] * (1.0f / QR);
    __syncthreads();

    float vs = 0.f;
    for (int c = tid; c < QR / 4; c += 256) {
        float4 v = p[c];
        float dx = v.x - mean, dy = v.y - mean, dz = v.z - mean, dw = v.w - mean;
        vs += dx * dx + dy * dy + dz * dz + dw * dw;
    }
    red[tid] = vs; __syncthreads();
    for (int o = 128; o > 0; o >>= 1) {
        if (tid < o) red[tid] += red[tid + o];
        __syncthreads();
    }
    float inv = rsqrtf(red[0] * (1.0f / QR) + LN_EPS);

    for (int c = tid; c < QR / 4; c += 256) {
        float4 v = p[c], gg = g4[c], bb = b4[c];
        v.x = (v.x - mean) * inv * gg.x + bb.x;
        v.y = (v.y - mean) * inv * gg.y + bb.y;
        v.z = (v.z - mean) * inv * gg.z + bb.z;
        v.w = (v.w - mean) * inv * gg.w + bb.w;
        p[c] = v;
    }
}

// ---------------- sim[b,h,i,j] = (1/sqrt(dh)) * q_h[i,:]·k_h[j,:] -----------------
__global__ __launch_bounds__(256) void sim_kernel()
{
    __shared__ float qs[64][97];
    __shared__ float ks[32][97];
    int jt = blockIdx.x, h = blockIdx.y, b = blockIdx.z;
    int tid = threadIdx.x;

    for (int idx = tid; idx < 64 * 96; idx += 256) {
        int i = idx / 96, c = idx % 96;
        qs[i][c] = g_q[(size_t)(b * NQ + i) * DD + h * DH + c];
    }
    for (int idx = tid; idx < 32 * 96; idx += 256) {
        int j = idx / 96, c = idx % 96;
        ks[j][c] = g_k[(size_t)(b * NN + jt * 32 + j) * DD + h * DH + c];
    }
    __syncthreads();

    int tx = tid & 15, ty = tid >> 4;
    float acc[4][2];
    #pragma unroll
    for (int ii = 0; ii < 4; ii++) { acc[ii][0] = 0.f; acc[ii][1] = 0.f; }

    #pragma unroll 4
    for (int c = 0; c < 96; c++) {
        float qv[4], kv[2];
        #pragma unroll
        for (int ii = 0; ii < 4; ii++) qv[ii] = qs[ty * 4 + ii][c];
        kv[0] = ks[tx * 2][c];
        kv[1] = ks[tx * 2 + 1][c];
        #pragma unroll
        for (int ii = 0; ii < 4; ii++) {
            acc[ii][0] = fmaf(qv[ii], kv[0], acc[ii][0]);
            acc[ii][1] = fmaf(qv[ii], kv[1], acc[ii][1]);
        }
    }

    const float sc = 0.10206207261596577f; // 96^-0.5
    #pragma unroll
    for (int ii = 0; ii < 4; ii++) {
        #pragma unroll
        for (int jj = 0; jj < 2; jj++) {
            int i = ty * 4 + ii, j = jt * 32 + tx * 2 + jj;
            g_sim[((size_t)(b * HH + h) * NQ + i) * NN + j] = acc[ii][jj] * sc;
        }
    }
}

// ---------------- softmax over j (row length 1024), in place on g_sim -------------
__global__ __launch_bounds__(256) void softmax_kernel()
{
    int row = blockIdx.x;
    float4* p = (float4*)(g_sim + (size_t)row * NN);  // 256 float4: one per thread
    __shared__ float red[256];
    int tid = threadIdx.x;

    float4 v = p[tid];
    float m = fmaxf(fmaxf(v.x, v.y), fmaxf(v.z, v.w));
    red[tid] = m; __syncthreads();
    for (int o = 128; o > 0; o >>= 1) {
        if (tid < o) red[tid] = fmaxf(red[tid], red[tid + o]);
        __syncthreads();
    }
    m = red[0]; __syncthreads();

    v.x = __expf(v.x - m); v.y = __expf(v.y - m);
    v.z = __expf(v.z - m); v.w = __expf(v.w - m);
    red[tid] = v.x + v.y + v.z + v.w; __syncthreads();
    for (int o = 128; o > 0; o >>= 1) {
        if (tid < o) red[tid] += red[tid + o];
        __syncthreads();
    }
    float inv = 1.0f / red[0];
    v.x *= inv; v.y *= inv; v.z *= inv; v.w *= inv;
    p[tid] = v;
}

// ---------------- t[b,i,h,r] = sum_j attn[b,h,i,j] * vmid[b,j,i,r] ----------------
__global__ __launch_bounds__(256) void t_kernel()
{
    int b = blockIdx.x >> 6, i = blockIdx.x & 63;
    __shared__ float attn_s[HH * NN];   // 32 KB
    __shared__ float red[4 * HH * 64];  // 8 KB
    int tid = threadIdx.x;

    for (int idx = tid; idx < HH * NN; idx += 256) {
        int h = idx >> 10, j = idx & 1023;
        attn_s[idx] = g_sim[((size_t)(b * HH + h) * NQ + i) * NN + j];
    }
    __syncthreads();

    int r = tid & 63, c4 = tid >> 6;
    float acc[8];
    #pragma unroll
    for (int h = 0; h < 8; h++) acc[h] = 0.f;

    const float* vp = g_h1 + (size_t)b * NN * QR + i * RANK + r;
    int j0 = c4 * 256;
    #pragma unroll 4
    for (int j = j0; j < j0 + 256; j++) {
        float vm = vp[(size_t)j * QR];
        #pragma unroll
        for (int h = 0; h < 8; h++)
            acc[h] = fmaf(attn_s[h * NN + j], vm, acc[h]);
    }
    #pragma unroll
    for (int h = 0; h < 8; h++) red[(c4 * 8 + h) * 64 + r] = acc[h];
    __syncthreads();

    for (int idx = tid; idx < 8 * 64; idx += 256) {
        int h = idx >> 6, r2 = idx & 63;
        float s = red[(0 * 8 + h) * 64 + r2] + red[(1 * 8 + h) * 64 + r2]
                + red[(2 * 8 + h) * 64 + r2] + red[(3 * 8 + h) * 64 + r2];
        g_t[((size_t)(b * NQ + i) * HH + h) * 64 + r2] = s;
    }
}

// ---------------- out_pre[b,i,d] = sum_r t[b,i,head(d),r] * Wc[i,r,d] -------------
__global__ __launch_bounds__(256) void conv_kernel(const float* __restrict__ Wc)
{
    int b = blockIdx.x >> 6, i = blockIdx.x & 63;
    __shared__ float ts[HH * RANK];
    int tid = threadIdx.x;
    for (int idx = tid; idx < HH * RANK; idx += 256)
        ts[idx] = g_t[(size_t)(b * NQ + i) * (HH * RANK) + idx];
    __syncthreads();

    for (int dd = tid; dd < DD; dd += 256) {
        int h = dd / DH;
        float acc = 0.f;
        const float* wp = Wc + (size_t)i * RANK * DD + dd;
        #pragma unroll 8
        for (int rr = 0; rr < RANK; rr++)
            acc = fmaf(ts[h * RANK + rr], wp[(size_t)rr * DD], acc);
        g_op[(size_t)(b * NQ + i) * DD + dd] = acc;
    }
}

// ---------------- launch ----------------
extern "C" void kernel_launch(void* const* d_in, const int* in_sizes, int n_in,
                              void* d_out, int out_size)
{
    const float* x       = (const float*)d_in[0];
    const float* context = (const float*)d_in[1];
    const float* Wq      = (const float*)d_in[2];
    const float* Wk      = (const float*)d_in[3];
    const float* Wv1     = (const float*)d_in[4];
    const float* ln_g    = (const float*)d_in[5];
    const float* ln_b    = (const float*)d_in[6];
    const float* Wc      = (const float*)d_in[7];
    const float* Wout    = (const float*)d_in[8];
    float* out = (float*)d_out;

    float *pq, *pk, *ph1, *pop;
    cudaGetSymbolAddress((void**)&pq,  g_q);
    cudaGetSymbolAddress((void**)&pk,  g_k);
    cudaGetSymbolAddress((void**)&ph1, g_h1);
    cudaGetSymbolAddress((void**)&pop, g_op);

    // h1 = context @ Wv1      [4096,768] @ [768,4096]  (dominant) - launch first
    tgemm128<<<dim3(QR / 128, (BB * NN) / 128), 256>>>(context, Wv1, ph1, BB * NN, QR, DD);
    // k = context @ Wk        [4096,768] @ [768,768]
    tgemm128<<<dim3(DD / 128, (BB * NN) / 128), 256>>>(context, Wk, pk, BB * NN, DD, DD);
    // q = x @ Wq              [256,768] @ [768,768]
    tgemm128<<<dim3(DD / 128, (BB * NQ) / 128), 256>>>(x, Wq, pq, BB * NQ, DD, DD);
    // LayerNorm rows of h1 (-> vmid)
    ln_kernel<<<BB * NN, 256>>>(ln_g, ln_b);
    // sim = scaled q·k per head
    sim_kernel<<<dim3(NN / 32, HH, BB), 256>>>();
    // softmax over keys
    softmax_kernel<<<BB * HH * NQ, 256>>>();
    // t = attn @ vmid (rank space, per query)
    t_kernel<<<BB * NQ, 256>>>();
    // out_pre = t contracted with Wc (rank -> d)
    conv_kernel<<<BB * NQ, 256>>>(Wc);
    // out = out_pre @ Wout    [256,768] @ [768,768]
    tgemm128<<<dim3(DD / 128, (BB * NQ) / 128), 256>>>(pop, Wout, out, BB * NQ, DD, DD);
}

// round 5
// speedup vs baseline: 2.9245x; 1.0896x over previous
#include <cuda_runtime.h>
#include <math.h>
#include <stdint.h>

#define BB 4
#define NQ 64
#define NN 1024
#define DD 768
#define HH 8
#define DH 96
#define RANK 64
#define QR 4096
#define LN_EPS 1e-5f

// ---------------- scratch (static device allocations; no cudaMalloc) ----------------
__device__ float g_q [BB*NQ*DD];             // 0.75 MB
__device__ float g_k [BB*NN*DD];             // 12.6 MB
__device__ float g_h1[(size_t)BB*NN*QR];     // 67 MB  (RAW h1; normalized on the fly)
__device__ float g_sim[(size_t)BB*HH*NQ*NN]; // 8.4 MB
__device__ float g_mu [BB*NN];
__device__ float g_inv[BB*NN];
__device__ float g_t [BB*NQ*HH*RANK];        // 0.5 MB
__device__ float g_op[BB*NQ*DD];             // 0.75 MB

// ---------------- tf32 helpers ----------------
__device__ __forceinline__ float to_tf32(float x) {
    uint32_t u;
    asm("cvt.rna.tf32.f32 %0, %1;" : "=r"(u) : "f"(x));
    return __uint_as_float(u);
}

__device__ __forceinline__ void mma_tf32(float* d, const uint32_t* a, const uint32_t* b) {
    asm volatile("mma.sync.aligned.m16n8k8.row.col.f32.tf32.tf32.f32 "
                 "{%0,%1,%2,%3}, {%4,%5,%6,%7}, {%8,%9}, {%0,%1,%2,%3};"
                 : "+f"(d[0]), "+f"(d[1]), "+f"(d[2]), "+f"(d[3])
                 : "r"(a[0]), "r"(a[1]), "r"(a[2]), "r"(a[3]),
                   "r"(b[0]), "r"(b[1]));
}

// ---------------- 128x128 tf32 tensor-core GEMM, double-buffered pipeline ----------
// Block: 256 threads = 8 warps (4 warp-rows x 2 warp-cols), warp tile 32x64.
// Dynamic smem: As[2][128][36] + Bs[2][32][136] = 71680 B.
// As frag LDS bank = (4g+tg)%32, Bs frag bank = (8tg+g)%32 -> conflict-free.
// One __syncthreads per K-iter; next chunk's LDGs issue before current compute.
#define AS(s,r,c) AsB[(s)*4608 + (r)*36 + (c)]
#define BS(s,r,c) BsB[(s)*4352 + (r)*136 + (c)]

__global__ __launch_bounds__(256) void tgemm128(const float* __restrict__ A,
                                                const float* __restrict__ Bm,
                                                float* __restrict__ C,
                                                int M, int Nn, int K)
{
    extern __shared__ float smem_dyn[];
    float* AsB = smem_dyn;            // 2 * 128 * 36
    float* BsB = smem_dyn + 9216;     // 2 * 32 * 136

    int tid  = threadIdx.x;
    int warp = tid >> 5, lane = tid & 31;
    int g = lane >> 2, tg = lane & 3;
    int wm = (warp >> 1) * 32;
    int wn = (warp & 1) * 64;
    int m0 = blockIdx.y * 128, n0 = blockIdx.x * 128;

    int arb = tid >> 3, ac = (tid & 7) * 4;   // A: rows arb + 32*l, cols ac..ac+3
    int brb = tid >> 5, bc = (tid & 31) * 4;  // B: rows brb + 8*l,  cols bc..bc+3

    float acc[2][8][4];
    #pragma unroll
    for (int mi = 0; mi < 2; mi++)
        #pragma unroll
        for (int ni = 0; ni < 8; ni++)
            #pragma unroll
            for (int c = 0; c < 4; c++) acc[mi][ni][c] = 0.f;

    float4 av[4], bv[4];

    // prologue: chunk 0 -> regs -> stage 0
    #pragma unroll
    for (int l = 0; l < 4; l++) {
        av[l] = *(const float4*)(A + (size_t)(m0 + arb + l * 32) * K + ac);
        bv[l] = *(const float4*)(Bm + (size_t)(brb + l * 8) * Nn + n0 + bc);
    }
    #pragma unroll
    for (int l = 0; l < 4; l++) {
        float4 a = av[l], b = bv[l];
        a.x = to_tf32(a.x); a.y = to_tf32(a.y); a.z = to_tf32(a.z); a.w = to_tf32(a.w);
        b.x = to_tf32(b.x); b.y = to_tf32(b.y); b.z = to_tf32(b.z); b.w = to_tf32(b.w);
        *(float4*)&AS(0, arb + l * 32, ac) = a;
        *(float4*)&BS(0, brb + l * 8, bc) = b;
    }
    __syncthreads();

    int nk = K >> 5;
    for (int it = 0; it < nk; it++) {
        int stage = it & 1;
        // prefetch next chunk (LDGs in flight during compute below)
        if (it + 1 < nk) {
            int kt = (it + 1) << 5;
            #pragma unroll
            for (int l = 0; l < 4; l++) {
                av[l] = *(const float4*)(A + (size_t)(m0 + arb + l * 32) * K + kt + ac);
                bv[l] = *(const float4*)(Bm + (size_t)(kt + brb + l * 8) * Nn + n0 + bc);
            }
        }

        #pragma unroll
        for (int ks = 0; ks < 4; ks++) {
            int kk = ks * 8;
            uint32_t af[2][4], bf[8][2];
            #pragma unroll
            for (int mi = 0; mi < 2; mi++) {
                int mr = wm + mi * 16 + g;
                af[mi][0] = __float_as_uint(AS(stage, mr,     kk + tg));
                af[mi][1] = __float_as_uint(AS(stage, mr + 8, kk + tg));
                af[mi][2] = __float_as_uint(AS(stage, mr,     kk + tg + 4));
                af[mi][3] = __float_as_uint(AS(stage, mr + 8, kk + tg + 4));
            }
            #pragma unroll
            for (int ni = 0; ni < 8; ni++) {
                int nc = wn + ni * 8 + g;
                bf[ni][0] = __float_as_uint(BS(stage, kk + tg,     nc));
                bf[ni][1] = __float_as_uint(BS(stage, kk + tg + 4, nc));
            }
            #pragma unroll
            for (int mi = 0; mi < 2; mi++)
                #pragma unroll
                for (int ni = 0; ni < 8; ni++)
                    mma_tf32(acc[mi][ni], af[mi], bf[ni]);
        }

        if (it + 1 < nk) {
            int ns = stage ^ 1;
            #pragma unroll
            for (int l = 0; l < 4; l++) {
                float4 a = av[l], b = bv[l];
                a.x = to_tf32(a.x); a.y = to_tf32(a.y); a.z = to_tf32(a.z); a.w = to_tf32(a.w);
                b.x = to_tf32(b.x); b.y = to_tf32(b.y); b.z = to_tf32(b.z); b.w = to_tf32(b.w);
                *(float4*)&AS(ns, arb + l * 32, ac) = a;
                *(float4*)&BS(ns, brb + l * 8, bc) = b;
            }
            __syncthreads();
        }
    }

    // epilogue: c0:(g,2tg) c1:(g,2tg+1) c2:(g+8,2tg) c3:(g+8,2tg+1)
    #pragma unroll
    for (int mi = 0; mi < 2; mi++) {
        int r0 = m0 + wm + mi * 16 + g;
        #pragma unroll
        for (int ni = 0; ni < 8; ni++) {
            int c = n0 + wn + ni * 8 + 2 * tg;
            *(float2*)(C + (size_t)r0 * Nn + c)       = make_float2(acc[mi][ni][0], acc[mi][ni][1]);
            *(float2*)(C + (size_t)(r0 + 8) * Nn + c) = make_float2(acc[mi][ni][2], acc[mi][ni][3]);
        }
    }
}

// ---------------- LN stats only: mean + rsqrt(var) per (b,n) row of g_h1 ----------
__global__ __launch_bounds__(256) void ln_stats()
{
    int row = blockIdx.x;
    const float4* p = (const float4*)(g_h1 + (size_t)row * QR);
    __shared__ float red[512];
    int tid = threadIdx.x;

    float s = 0.f, q = 0.f;
    for (int c = tid; c < QR / 4; c += 256) {
        float4 v = p[c];
        s += v.x + v.y + v.z + v.w;
        q += v.x * v.x + v.y * v.y + v.z * v.z + v.w * v.w;
    }
    red[tid] = s; red[256 + tid] = q; __syncthreads();
    for (int o = 128; o > 0; o >>= 1) {
        if (tid < o) { red[tid] += red[tid + o]; red[256 + tid] += red[256 + tid + o]; }
        __syncthreads();
    }
    if (tid == 0) {
        float mean = red[0] * (1.0f / QR);
        float var  = red[256] * (1.0f / QR) - mean * mean;
        g_mu[row]  = mean;
        g_inv[row] = rsqrtf(var + LN_EPS);
    }
}

// ---------------- sim[b,h,i,j] = (1/sqrt(dh)) * q_h[i,:]·k_h[j,:] -----------------
__global__ __launch_bounds__(256) void sim_kernel()
{
    __shared__ float qs[64][97];
    __shared__ float ks[32][97];
    int jt = blockIdx.x, h = blockIdx.y, b = blockIdx.z;
    int tid = threadIdx.x;

    for (int idx = tid; idx < 64 * 96; idx += 256) {
        int i = idx / 96, c = idx % 96;
        qs[i][c] = g_q[(size_t)(b * NQ + i) * DD + h * DH + c];
    }
    for (int idx = tid; idx < 32 * 96; idx += 256) {
        int j = idx / 96, c = idx % 96;
        ks[j][c] = g_k[(size_t)(b * NN + jt * 32 + j) * DD + h * DH + c];
    }
    __syncthreads();

    int tx = tid & 15, ty = tid >> 4;
    float acc[4][2];
    #pragma unroll
    for (int ii = 0; ii < 4; ii++) { acc[ii][0] = 0.f; acc[ii][1] = 0.f; }

    #pragma unroll 4
    for (int c = 0; c < 96; c++) {
        float qv[4], kv[2];
        #pragma unroll
        for (int ii = 0; ii < 4; ii++) qv[ii] = qs[ty * 4 + ii][c];
        kv[0] = ks[tx * 2][c];
        kv[1] = ks[tx * 2 + 1][c];
        #pragma unroll
        for (int ii = 0; ii < 4; ii++) {
            acc[ii][0] = fmaf(qv[ii], kv[0], acc[ii][0]);
            acc[ii][1] = fmaf(qv[ii], kv[1], acc[ii][1]);
        }
    }

    const float sc = 0.10206207261596577f; // 96^-0.5
    #pragma unroll
    for (int ii = 0; ii < 4; ii++) {
        #pragma unroll
        for (int jj = 0; jj < 2; jj++) {
            int i = ty * 4 + ii, j = jt * 32 + tx * 2 + jj;
            g_sim[((size_t)(b * HH + h) * NQ + i) * NN + j] = acc[ii][jj] * sc;
        }
    }
}

// ---------------- softmax over j (row length 1024), in place on g_sim -------------
__global__ __launch_bounds__(256) void softmax_kernel()
{
    int row = blockIdx.x;
    float4* p = (float4*)(g_sim + (size_t)row * NN);
    __shared__ float red[256];
    int tid = threadIdx.x;

    float4 v = p[tid];
    float m = fmaxf(fmaxf(v.x, v.y), fmaxf(v.z, v.w));
    red[tid] = m; __syncthreads();
    for (int o = 128; o > 0; o >>= 1) {
        if (tid < o) red[tid] = fmaxf(red[tid], red[tid + o]);
        __syncthreads();
    }
    m = red[0]; __syncthreads();

    v.x = __expf(v.x - m); v.y = __expf(v.y - m);
    v.z = __expf(v.z - m); v.w = __expf(v.w - m);
    red[tid] = v.x + v.y + v.z + v.w; __syncthreads();
    for (int o = 128; o > 0; o >>= 1) {
        if (tid < o) red[tid] += red[tid + o];
        __syncthreads();
    }
    float inv = 1.0f / red[0];
    v.x *= inv; v.y *= inv; v.z *= inv; v.w *= inv;
    p[tid] = v;
}

// ---- t[b,i,h,r] = gam(i,r) * sum_j attn[b,h,i,j]*(h1[b,j,i,r]-mu)*inv + bet(i,r) --
// (uses sum_j attn = 1 to pull gamma/beta out of the contraction)
__global__ __launch_bounds__(256) void t_kernel(const float* __restrict__ gam,
                                                const float* __restrict__ bet)
{
    int b = blockIdx.x >> 6, i = blockIdx.x & 63;
    __shared__ float attn_s[HH * NN];   // 32 KB
    __shared__ float aux[2048];         // mu[0..1023], inv[1024..2047]; reused as red
    int tid = threadIdx.x;

    for (int idx = tid; idx < HH * NN; idx += 256) {
        int h = idx >> 10, j = idx & 1023;
        attn_s[idx] = g_sim[((size_t)(b * HH + h) * NQ + i) * NN + j];
    }
    for (int j = tid; j < NN; j += 256) {
        aux[j]        = g_mu [b * NN + j];
        aux[1024 + j] = g_inv[b * NN + j];
    }
    __syncthreads();

    int r = tid & 63, c4 = tid >> 6;
    float gamma = gam[i * RANK + r], beta = bet[i * RANK + r];
    float acc[8];
    #pragma unroll
    for (int h = 0; h < 8; h++) acc[h] = 0.f;

    const float* vp = g_h1 + (size_t)b * NN * QR + i * RANK + r;
    int j0 = c4 * 256;
    #pragma unroll 4
    for (int j = j0; j < j0 + 256; j++) {
        float vm = (vp[(size_t)j * QR] - aux[j]) * aux[1024 + j];
        #pragma unroll
        for (int h = 0; h < 8; h++)
            acc[h] = fmaf(attn_s[h * NN + j], vm, acc[h]);
    }
    __syncthreads();   // done with mu/inv; reuse aux as reduction buffer
    #pragma unroll
    for (int h = 0; h < 8; h++) aux[(c4 * 8 + h) * 64 + r] = acc[h];
    __syncthreads();

    for (int idx = tid; idx < 8 * 64; idx += 256) {
        int h = idx >> 6, r2 = idx & 63;
        float s = aux[(0 * 8 + h) * 64 + r2] + aux[(1 * 8 + h) * 64 + r2]
                + aux[(2 * 8 + h) * 64 + r2] + aux[(3 * 8 + h) * 64 + r2];
        g_t[((size_t)(b * NQ + i) * HH + h) * 64 + r2] =
            gam[i * RANK + r2] * s + bet[i * RANK + r2];
    }
}

// ---------------- out_pre[b,i,d] = sum_r t[b,i,head(d),r] * Wc[i,r,d] -------------
__global__ __launch_bounds__(256) void conv_kernel(const float* __restrict__ Wc)
{
    int b = blockIdx.x >> 6, i = blockIdx.x & 63;
    __shared__ float ts[HH * RANK];
    int tid = threadIdx.x;
    for (int idx = tid; idx < HH * RANK; idx += 256)
        ts[idx] = g_t[(size_t)(b * NQ + i) * (HH * RANK) + idx];
    __syncthreads();

    for (int dd = tid; dd < DD; dd += 256) {
        int h = dd / DH;
        float acc = 0.f;
        const float* wp = Wc + (size_t)i * RANK * DD + dd;
        #pragma unroll 8
        for (int rr = 0; rr < RANK; rr++)
            acc = fmaf(ts[h * RANK + rr], wp[(size_t)rr * DD], acc);
        g_op[(size_t)(b * NQ + i) * DD + dd] = acc;
    }
}

// ---------------- launch ----------------
#define TGEMM_SMEM 71680

extern "C" void kernel_launch(void* const* d_in, const int* in_sizes, int n_in,
                              void* d_out, int out_size)
{
    const float* x       = (const float*)d_in[0];
    const float* context = (const float*)d_in[1];
    const float* Wq      = (const float*)d_in[2];
    const float* Wk      = (const float*)d_in[3];
    const float* Wv1     = (const float*)d_in[4];
    const float* ln_g    = (const float*)d_in[5];
    const float* ln_b    = (const float*)d_in[6];
    const float* Wc      = (const float*)d_in[7];
    const float* Wout    = (const float*)d_in[8];
    float* out = (float*)d_out;

    cudaFuncSetAttribute(tgemm128, cudaFuncAttributeMaxDynamicSharedMemorySize, TGEMM_SMEM);

    float *pq, *pk, *ph1, *pop;
    cudaGetSymbolAddress((void**)&pq,  g_q);
    cudaGetSymbolAddress((void**)&pk,  g_k);
    cudaGetSymbolAddress((void**)&ph1, g_h1);
    cudaGetSymbolAddress((void**)&pop, g_op);

    // h1 = context @ Wv1      [4096,768] @ [768,4096]  (dominant)
    tgemm128<<<dim3(QR / 128, (BB * NN) / 128), 256, TGEMM_SMEM>>>(context, Wv1, ph1, BB * NN, QR, DD);
    // k = context @ Wk        [4096,768] @ [768,768]
    tgemm128<<<dim3(DD / 128, (BB * NN) / 128), 256, TGEMM_SMEM>>>(context, Wk, pk, BB * NN, DD, DD);
    // q = x @ Wq              [256,768] @ [768,768]
    tgemm128<<<dim3(DD / 128, (BB * NQ) / 128), 256, TGEMM_SMEM>>>(x, Wq, pq, BB * NQ, DD, DD);
    // LN statistics (normalization fused into t_kernel)
    ln_stats<<<BB * NN, 256>>>();
    // sim = scaled q·k per head
    sim_kernel<<<dim3(NN / 32, HH, BB), 256>>>();
    // softmax over keys
    softmax_kernel<<<BB * HH * NQ, 256>>>();
    // t = attn @ LN(vmid) (rank space, per query; LN affine fused)
    t_kernel<<<BB * NQ, 256>>>(ln_g, ln_b);
    // out_pre = t contracted with Wc (rank -> d)
    conv_kernel<<<BB * NQ, 256>>>(Wc);
    // out = out_pre @ Wout    [256,768] @ [768,768]
    tgemm128<<<dim3(DD / 128, (BB * NQ) / 128), 256, TGEMM_SMEM>>>(pop, Wout, out, BB * NQ, DD, DD);
}